// round 5
// baseline (speedup 1.0000x reference)
#include <cuda_runtime.h>
#include <cstdint>

// ============================================================================
// SharedMatrix (butterfly block-sparse matmul) on GB300, PLAIN sm_103 target.
//   x : [8192, 4096] f32          (d_in[0])
//   w : [4096, 5, 256] f32        (d_in[1])
//   fi: [16, 5] int32             (d_in[2])
//   out:[8192, 4096] f32
//
// 16 GEMMs: M=8192, N=256, K=1280 via mma.sync.m16n8k8.tf32.
// R5 vs R4: CTA tile 128x128, 256 thr, 3x32KB stages -> 2 CTAs/SM (two
// independent barrier domains fill HMMA bubbles); x cvt.rna dropped (HW
// truncation), weights remain RNA-rounded in repack.
// ============================================================================

static constexpr int NKIT = 40;                    // 5 blocks x 8 chunks of k=32
static constexpr int STAGES = 3;
static constexpr uint32_t A_BYTES = 16384;         // 128 x 32 x 4
static constexpr uint32_t B_BYTES = 16384;         // 128 x 32 x 4
static constexpr uint32_t STAGE_BYTES = A_BYTES + B_BYTES;      // 32KB
static constexpr uint32_t SMEM_TOTAL = STAGES * STAGE_BYTES + 1024;  // 99328

// Repacked gathered tf32(RNA) weights, pre-swizzled 16KB SMEM images:
// g_Bp[((o*2+nh)*40+it)*4096 + swz(nl*128 + k*4)/4]   (32*40*16KB = 20.97 MB)
__device__ float g_Bp[32 * NKIT * 4096];

// ---------------------------------------------------------------------------
__device__ __forceinline__ uint32_t smem_u32(const void* p) {
    uint32_t a;
    asm("{ .reg .u64 t; cvta.to.shared.u64 t, %1; cvt.u32.u64 %0, t; }"
        : "=r"(a) : "l"(p));
    return a;
}
__device__ __forceinline__ void cpasync16(uint32_t dst, const float* src) {
    asm volatile("cp.async.cg.shared.global [%0], [%1], 16;"
                 :: "r"(dst), "l"(src) : "memory");
}
__device__ __forceinline__ void cp_commit() {
    asm volatile("cp.async.commit_group;" ::: "memory");
}
template <int N>
__device__ __forceinline__ void cp_wait() {
    asm volatile("cp.async.wait_group %0;" :: "n"(N) : "memory");
}
__device__ __forceinline__ void ldsm4(uint32_t& r0, uint32_t& r1,
                                      uint32_t& r2, uint32_t& r3, uint32_t a) {
    asm volatile("ldmatrix.sync.aligned.m8n8.x4.shared.b16 {%0,%1,%2,%3}, [%4];"
                 : "=r"(r0), "=r"(r1), "=r"(r2), "=r"(r3) : "r"(a));
}
__device__ __forceinline__ void mma_tf32(float* c, const uint32_t* a,
                                         uint32_t b0, uint32_t b1) {
    asm volatile(
        "mma.sync.aligned.m16n8k8.row.col.f32.tf32.tf32.f32 "
        "{%0,%1,%2,%3}, {%4,%5,%6,%7}, {%8,%9}, {%0,%1,%2,%3};"
        : "+f"(c[0]), "+f"(c[1]), "+f"(c[2]), "+f"(c[3])
        : "r"(a[0]), "r"(a[1]), "r"(a[2]), "r"(a[3]), "r"(b0), "r"(b1));
}

// ---------------------------------------------------------------------------
// repack: gather + transpose + RNA-round weights into pre-swizzled 16KB tiles
//   grid: (ntile=8, kchunk=8, o*5+a=80), block (32, 8)
// ---------------------------------------------------------------------------
__global__ void __launch_bounds__(256, 4)
repack_kernel(const float* __restrict__ w, const int* __restrict__ fi) {
    const int oa = blockIdx.z;
    const int o = oa / 5, a = oa % 5;
    const int f = fi[o * 5 + a];
    const int g = f / 5, slot = f % 5;
    const int k0 = blockIdx.y * 32;
    const int n0 = blockIdx.x * 32;
    const int c = blockIdx.y;
    const int nh = n0 >> 7;            // which 128-col half image

    __shared__ float t[32][33];
    const int tx = threadIdx.x, ty = threadIdx.y;

    #pragma unroll
    for (int i = 0; i < 4; ++i) {
        int k = ty + i * 8;
        float v = w[((size_t)(g * 256 + k0 + k) * 5 + slot) * 256 + n0 + tx];
        uint32_t u;
        asm("cvt.rna.tf32.f32 %0, %1;" : "=r"(u) : "f"(v));
        t[k][tx] = __uint_as_float(u);
    }
    __syncthreads();

    float* tile = g_Bp + ((size_t)(o * 2 + nh) * NKIT + a * 8 + c) * 4096;
    #pragma unroll
    for (int i = 0; i < 4; ++i) {
        int nl = (n0 & 127) + ty + i * 8;
        uint32_t off = (uint32_t)nl * 128u + (uint32_t)tx * 4u;
        uint32_t swz = off ^ ((off >> 3) & 0x70u);
        tile[swz >> 2] = t[tx][ty + i * 8];
    }
}

// ---------------------------------------------------------------------------
// GEMM: grid (o*2+nh=32, mtile=64), 256 threads, CTA tile 128(M) x 128(N)
//   8 warps in 4(m) x 2(n) grid of 32x64 warp tiles; 2 CTAs/SM.
// ---------------------------------------------------------------------------
__global__ void __launch_bounds__(256, 2)
gemm_kernel(const float* __restrict__ x, const int* __restrict__ fi,
            float* __restrict__ out) {
    extern __shared__ char smem_raw[];
    const uint32_t sb = (smem_u32(smem_raw) + 1023u) & ~1023u;
    const int tid = (int)threadIdx.x;
    const int wid = tid >> 5;
    const int lane = tid & 31;
    const int o = (int)blockIdx.x >> 1;
    const int nh = (int)blockIdx.x & 1;
    const int m_base = (int)blockIdx.y * 128;
    const int warp_m = wid >> 1;   // 0..3  (32 rows each)
    const int warp_n = wid & 1;    // 0..1  (64 cols each)

    int colf[5];
    #pragma unroll
    for (int a = 0; a < 5; ++a) colf[a] = (fi[o * 5 + a] / 5) << 8;

    // ---- producer addressing (all 256 threads) ----
    // A: 128 rows x 32 floats = 1024 16B segs -> 4 per thread
    const int arow = tid >> 1;                 // 0..127
    const int asub = (tid & 1) * 4;            // segments asub..asub+3 (of 8)
    const float* xrow = x + (size_t)(m_base + arow) * 4096;
    const uint32_t adst_base = (uint32_t)arow * 128u;
    const uint32_t axor = (uint32_t)(arow & 7) << 4;
    // B: 16KB = 1024 segs -> 4 per thread (raw image copy)
    const float* bsrc0 = g_Bp + (size_t)blockIdx.x * NKIT * 4096 + tid * 4;

    auto issue = [&](int it, int s) {
        const uint32_t st = sb + (uint32_t)s * STAGE_BYTES;
        const int col = colf[it >> 3] + (it & 7) * 32;
        const float* asrc = xrow + col + asub * 4;
        #pragma unroll
        for (int j = 0; j < 4; ++j) {
            uint32_t doff = (((uint32_t)(asub + j) * 16u) ^ axor);
            cpasync16(st + adst_base + doff, asrc + j * 4);
        }
        const float* bsrc = bsrc0 + (size_t)it * 4096;
        #pragma unroll
        for (int j = 0; j < 4; ++j)
            cpasync16(st + A_BYTES + (uint32_t)tid * 16u + (uint32_t)j * 4096u,
                      bsrc + j * 1024);
        cp_commit();
    };

    // ---- consumer lane addressing ----
    const int a_tile = lane >> 3;              // 0..3
    const int a_row_l = ((a_tile & 1) << 3) + (lane & 7);
    const int a_ktile = a_tile >> 1;           // 0..1 (k half of 16)
    const int b_khalf = (lane >> 3) & 1;
    const int b_row_l = (((lane >> 4) & 1) << 3) + (lane & 7);

    float c[2][8][4];
    #pragma unroll
    for (int mi = 0; mi < 2; ++mi)
        #pragma unroll
        for (int ni = 0; ni < 8; ++ni)
            #pragma unroll
            for (int q = 0; q < 4; ++q) c[mi][ni][q] = 0.0f;

    // prologue
    issue(0, 0); issue(1, 1);

    const uint32_t a_warp_off = (uint32_t)(warp_m * 32) * 128u;
    const uint32_t b_warp_off = A_BYTES + (uint32_t)(warp_n * 64) * 128u;

    int buf = 0;
    for (int it = 0; it < NKIT; ++it) {
        cp_wait<1>();
        __syncthreads();
        if (it + 2 < NKIT) {
            int nb = buf + 2; if (nb >= 3) nb -= 3;
            issue(it + 2, nb);
        } else {
            cp_commit();   // keep group numbering advancing
        }

        const uint32_t st = sb + (uint32_t)buf * STAGE_BYTES;
        const uint32_t abw = st + a_warp_off;
        const uint32_t bbw = st + b_warp_off;

        #pragma unroll
        for (int ks = 0; ks < 4; ++ks) {
            uint32_t af[2][4];
            #pragma unroll
            for (int mi = 0; mi < 2; ++mi) {
                int row = mi * 16 + a_row_l;
                uint32_t off = (uint32_t)((ks * 2 + a_ktile) * 16) ^
                               ((uint32_t)(row & 7) << 4);
                ldsm4(af[mi][0], af[mi][1], af[mi][2], af[mi][3],
                      abw + (uint32_t)row * 128u + off);
            }
            // NOTE: no cvt.rna on A fragments — HW HMMA truncates f32->tf32;
            // weights are RNA-rounded in repack.
            uint32_t bf[4][4];
            #pragma unroll
            for (int ni2 = 0; ni2 < 4; ++ni2) {
                int n = ni2 * 16 + b_row_l;
                uint32_t off = (uint32_t)((ks * 2 + b_khalf) * 16) ^
                               ((uint32_t)(n & 7) << 4);
                ldsm4(bf[ni2][0], bf[ni2][1], bf[ni2][2], bf[ni2][3],
                      bbw + (uint32_t)n * 128u + off);
            }

            #pragma unroll
            for (int mi = 0; mi < 2; ++mi)
                #pragma unroll
                for (int ni = 0; ni < 8; ++ni) {
                    const uint32_t* bp = &bf[ni >> 1][(ni & 1) * 2];
                    mma_tf32(c[mi][ni], af[mi], bp[0], bp[1]);
                }
        }
        if (++buf == 3) buf = 0;
    }

    // ---- epilogue: direct stores ----
    const int g = lane >> 2, t4 = lane & 3;
    const int row0 = m_base + warp_m * 32 + g;
    const int col0 = o * 256 + nh * 128 + warp_n * 64 + t4 * 2;
    #pragma unroll
    for (int mi = 0; mi < 2; ++mi) {
        #pragma unroll
        for (int ni = 0; ni < 8; ++ni) {
            float* p0 = out + (size_t)(row0 + mi * 16) * 4096 + col0 + ni * 8;
            float* p1 = p0 + 8 * 4096;
            *reinterpret_cast<float2*>(p0) =
                make_float2(c[mi][ni][0], c[mi][ni][1]);
            *reinterpret_cast<float2*>(p1) =
                make_float2(c[mi][ni][2], c[mi][ni][3]);
        }
    }
}

// ---------------------------------------------------------------------------
extern "C" void kernel_launch(void* const* d_in, const int* in_sizes, int n_in,
                              void* d_out, int out_size) {
    const float* x  = (const float*)d_in[0];
    const float* w  = (const float*)d_in[1];
    const int*   fi = (const int*)d_in[2];
    float* out = (float*)d_out;

    repack_kernel<<<dim3(8, 8, 80), dim3(32, 8)>>>(w, fi);

    cudaFuncSetAttribute(gemm_kernel,
                         cudaFuncAttributeMaxDynamicSharedMemorySize, SMEM_TOTAL);
    gemm_kernel<<<dim3(32, 64), 256, SMEM_TOTAL>>>(x, fi, out);
}

// round 6
// speedup vs baseline: 1.0823x; 1.0823x over previous
#include <cuda_runtime.h>
#include <cstdint>

// ============================================================================
// SharedMatrix (butterfly block-sparse matmul) on GB300, PLAIN sm_103 target.
//   x : [8192, 4096] f32          (d_in[0])
//   w : [4096, 5, 256] f32        (d_in[1])
//   fi: [16, 5] int32             (d_in[2])
//   out:[8192, 4096] f32
//
// 16 GEMMs: M=8192, N=256, K=1280 via mma.sync.m16n8k8.tf32.
// R6 vs R5: 1 CTA/SM (launch_bounds(256,1) -> ~150 regs headroom), 4 stages,
// register ping-pong of ldmatrix fragments so LDS latency hides under MMA
// within each warp (kills the correlated loop-head stalls).
// ============================================================================

static constexpr int NKIT = 40;                    // 5 blocks x 8 chunks of k=32
static constexpr uint32_t A_BYTES = 16384;         // 128 x 32 x 4
static constexpr uint32_t B_BYTES = 16384;         // 128 x 32 x 4
static constexpr uint32_t STAGE_BYTES = A_BYTES + B_BYTES;      // 32KB
static constexpr uint32_t SMEM_TOTAL = 4 * STAGE_BYTES + 1024;  // 132096

// Repacked gathered tf32(RNA) weights, pre-swizzled 16KB SMEM images:
// g_Bp[((o*2+nh)*40+it)*4096 + swz(nl*128 + k*4)/4]   (32*40*16KB = 20.97 MB)
__device__ float g_Bp[32 * NKIT * 4096];

// ---------------------------------------------------------------------------
__device__ __forceinline__ uint32_t smem_u32(const void* p) {
    uint32_t a;
    asm("{ .reg .u64 t; cvta.to.shared.u64 t, %1; cvt.u32.u64 %0, t; }"
        : "=r"(a) : "l"(p));
    return a;
}
__device__ __forceinline__ void cpasync16(uint32_t dst, const float* src) {
    asm volatile("cp.async.cg.shared.global [%0], [%1], 16;"
                 :: "r"(dst), "l"(src) : "memory");
}
__device__ __forceinline__ void cp_commit() {
    asm volatile("cp.async.commit_group;" ::: "memory");
}
template <int N>
__device__ __forceinline__ void cp_wait() {
    asm volatile("cp.async.wait_group %0;" :: "n"(N) : "memory");
}
__device__ __forceinline__ void ldsm4(uint32_t* r, uint32_t a) {
    asm volatile("ldmatrix.sync.aligned.m8n8.x4.shared.b16 {%0,%1,%2,%3}, [%4];"
                 : "=r"(r[0]), "=r"(r[1]), "=r"(r[2]), "=r"(r[3]) : "r"(a));
}
__device__ __forceinline__ void mma_tf32(float* c, const uint32_t* a,
                                         uint32_t b0, uint32_t b1) {
    asm volatile(
        "mma.sync.aligned.m16n8k8.row.col.f32.tf32.tf32.f32 "
        "{%0,%1,%2,%3}, {%4,%5,%6,%7}, {%8,%9}, {%0,%1,%2,%3};"
        : "+f"(c[0]), "+f"(c[1]), "+f"(c[2]), "+f"(c[3])
        : "r"(a[0]), "r"(a[1]), "r"(a[2]), "r"(a[3]), "r"(b0), "r"(b1));
}

// ---------------------------------------------------------------------------
// repack: gather + transpose + RNA-round weights into pre-swizzled 16KB tiles
//   grid: (ntile=8, kchunk=8, o*5+a=80), block (32, 8)
// ---------------------------------------------------------------------------
__global__ void __launch_bounds__(256, 4)
repack_kernel(const float* __restrict__ w, const int* __restrict__ fi) {
    const int oa = blockIdx.z;
    const int o = oa / 5, a = oa % 5;
    const int f = fi[o * 5 + a];
    const int g = f / 5, slot = f % 5;
    const int k0 = blockIdx.y * 32;
    const int n0 = blockIdx.x * 32;
    const int c = blockIdx.y;
    const int nh = n0 >> 7;

    __shared__ float t[32][33];
    const int tx = threadIdx.x, ty = threadIdx.y;

    #pragma unroll
    for (int i = 0; i < 4; ++i) {
        int k = ty + i * 8;
        float v = w[((size_t)(g * 256 + k0 + k) * 5 + slot) * 256 + n0 + tx];
        uint32_t u;
        asm("cvt.rna.tf32.f32 %0, %1;" : "=r"(u) : "f"(v));
        t[k][tx] = __uint_as_float(u);
    }
    __syncthreads();

    float* tile = g_Bp + ((size_t)(o * 2 + nh) * NKIT + a * 8 + c) * 4096;
    #pragma unroll
    for (int i = 0; i < 4; ++i) {
        int nl = (n0 & 127) + ty + i * 8;
        uint32_t off = (uint32_t)nl * 128u + (uint32_t)tx * 4u;
        uint32_t swz = off ^ ((off >> 3) & 0x70u);
        tile[swz >> 2] = t[tx][ty + i * 8];
    }
}

// ---------------------------------------------------------------------------
// GEMM: grid (o*2+nh=32, mtile=64), 256 threads, CTA tile 128(M) x 128(N)
//   8 warps in 4(m) x 2(n) grid of 32x64 warp tiles; register-pingponged frags
// ---------------------------------------------------------------------------
__global__ void __launch_bounds__(256, 1)
gemm_kernel(const float* __restrict__ x, const int* __restrict__ fi,
            float* __restrict__ out) {
    extern __shared__ char smem_raw[];
    const uint32_t sb = (smem_u32(smem_raw) + 1023u) & ~1023u;
    const int tid = (int)threadIdx.x;
    const int wid = tid >> 5;
    const int lane = tid & 31;
    const int o = (int)blockIdx.x >> 1;
    const int nh = (int)blockIdx.x & 1;
    const int m_base = (int)blockIdx.y * 128;
    const int warp_m = wid >> 1;   // 0..3  (32 rows each)
    const int warp_n = wid & 1;    // 0..1  (64 cols each)

    int colf[5];
    #pragma unroll
    for (int a = 0; a < 5; ++a) colf[a] = (fi[o * 5 + a] / 5) << 8;

    // ---- producer addressing (all 256 threads) ----
    const int arow = tid >> 1;                 // 0..127
    const int asub = (tid & 1) * 4;            // segments asub..asub+3 (of 8)
    const float* xrow = x + (size_t)(m_base + arow) * 4096;
    const uint32_t adst_base = (uint32_t)arow * 128u;
    const uint32_t axor = (uint32_t)(arow & 7) << 4;
    const float* bsrc0 = g_Bp + (size_t)blockIdx.x * NKIT * 4096 + tid * 4;

    auto issue = [&](int it, uint32_t s) {
        const uint32_t st = sb + s * STAGE_BYTES;
        const int col = colf[it >> 3] + (it & 7) * 32;
        const float* asrc = xrow + col + asub * 4;
        #pragma unroll
        for (int j = 0; j < 4; ++j) {
            uint32_t doff = (((uint32_t)(asub + j) * 16u) ^ axor);
            cpasync16(st + adst_base + doff, asrc + j * 4);
        }
        const float* bsrc = bsrc0 + (size_t)it * 4096;
        #pragma unroll
        for (int j = 0; j < 4; ++j)
            cpasync16(st + A_BYTES + (uint32_t)tid * 16u + (uint32_t)j * 4096u,
                      bsrc + j * 1024);
        cp_commit();
    };

    // ---- consumer lane addressing ----
    const int a_tile = lane >> 3;
    const int a_row_l = ((a_tile & 1) << 3) + (lane & 7);
    const int a_ktile = a_tile >> 1;
    const int b_khalf = (lane >> 3) & 1;
    const int b_row_l = (((lane >> 4) & 1) << 3) + (lane & 7);

    const uint32_t a_warp_off = (uint32_t)(warp_m * 32) * 128u;
    const uint32_t b_warp_off = A_BYTES + (uint32_t)(warp_n * 64) * 128u;

    float c[2][8][4];
    #pragma unroll
    for (int mi = 0; mi < 2; ++mi)
        #pragma unroll
        for (int ni = 0; ni < 8; ++ni)
            #pragma unroll
            for (int q = 0; q < 4; ++q) c[mi][ni][q] = 0.0f;

    uint32_t af[2][2][4];   // [pingpong][mi][frag]
    uint32_t bf[2][4][4];   // [pingpong][ni2][frag]

    auto load_frags = [&](uint32_t st, int ks, int pb) {
        const uint32_t abw = st + a_warp_off;
        const uint32_t bbw = st + b_warp_off;
        #pragma unroll
        for (int mi = 0; mi < 2; ++mi) {
            int row = mi * 16 + a_row_l;
            uint32_t off = (uint32_t)((ks * 2 + a_ktile) * 16) ^
                           ((uint32_t)(row & 7) << 4);
            ldsm4(af[pb][mi], abw + (uint32_t)row * 128u + off);
        }
        #pragma unroll
        for (int ni2 = 0; ni2 < 4; ++ni2) {
            int n = ni2 * 16 + b_row_l;
            uint32_t off = (uint32_t)((ks * 2 + b_khalf) * 16) ^
                           ((uint32_t)(n & 7) << 4);
            ldsm4(bf[pb][ni2], bbw + (uint32_t)n * 128u + off);
        }
    };

    auto mma_group = [&](int pb) {
        #pragma unroll
        for (int mi = 0; mi < 2; ++mi)
            #pragma unroll
            for (int ni = 0; ni < 8; ++ni) {
                const uint32_t* bp = &bf[pb][ni >> 1][(ni & 1) * 2];
                mma_tf32(c[mi][ni], af[pb][mi], bp[0], bp[1]);
            }
    };

    // prologue: fill 3 stages, land frags for stage 0 / ks 0
    issue(0, 0); issue(1, 1); issue(2, 2);
    cp_wait<2>();
    __syncthreads();
    load_frags(sb, 0, 0);

    #pragma unroll 4
    for (int it = 0; it < NKIT; ++it) {
        const uint32_t buf = (uint32_t)(it & 3);
        const uint32_t st = sb + buf * STAGE_BYTES;

        if (it + 3 < NKIT) issue(it + 3, (uint32_t)((it + 3) & 3));
        else cp_commit();   // keep group numbering advancing

        // ks 0..3 with register ping-pong: load ks+1 while MMAing ks
        load_frags(st, 1, 1);  mma_group(0);
        load_frags(st, 2, 0);  mma_group(1);
        load_frags(st, 3, 1);  mma_group(0);
        mma_group(1);

        cp_wait<2>();
        __syncthreads();
        if (it + 1 < NKIT)
            load_frags(sb + (uint32_t)((it + 1) & 3) * STAGE_BYTES, 0, 0);
    }

    // ---- epilogue: direct stores ----
    const int g = lane >> 2, t4 = lane & 3;
    const int row0 = m_base + warp_m * 32 + g;
    const int col0 = o * 256 + nh * 128 + warp_n * 64 + t4 * 2;
    #pragma unroll
    for (int mi = 0; mi < 2; ++mi) {
        #pragma unroll
        for (int ni = 0; ni < 8; ++ni) {
            float* p0 = out + (size_t)(row0 + mi * 16) * 4096 + col0 + ni * 8;
            float* p1 = p0 + 8 * 4096;
            *reinterpret_cast<float2*>(p0) =
                make_float2(c[mi][ni][0], c[mi][ni][1]);
            *reinterpret_cast<float2*>(p1) =
                make_float2(c[mi][ni][2], c[mi][ni][3]);
        }
    }
}

// ---------------------------------------------------------------------------
extern "C" void kernel_launch(void* const* d_in, const int* in_sizes, int n_in,
                              void* d_out, int out_size) {
    const float* x  = (const float*)d_in[0];
    const float* w  = (const float*)d_in[1];
    const int*   fi = (const int*)d_in[2];
    float* out = (float*)d_out;

    repack_kernel<<<dim3(8, 8, 80), dim3(32, 8)>>>(w, fi);

    cudaFuncSetAttribute(gemm_kernel,
                         cudaFuncAttributeMaxDynamicSharedMemorySize, SMEM_TOTAL);
    gemm_kernel<<<dim3(32, 64), 256, SMEM_TOTAL>>>(x, fi, out);
}

// round 7
// speedup vs baseline: 1.2704x; 1.1738x over previous
#include <cuda_runtime.h>
#include <cstdint>

// ============================================================================
// SharedMatrix (butterfly block-sparse matmul) on GB300, PLAIN sm_103 target.
//   x : [8192, 4096] f32          (d_in[0])
//   w : [4096, 5, 256] f32        (d_in[1])
//   fi: [16, 5] int32             (d_in[2])
//   out:[8192, 4096] f32
//
// 16 GEMMs: M=8192, N=256, K=1280 via mma.sync.m16n8k8.tf32.
// R7 vs R6: warp tile 64x64 (was 32x64) cuts LDSM fragment traffic 33%
// (crossbar was co-saturated with the tensor pipe at 32x64). CTA tile
// 128x256, 8 warps 2(m)x4(n), register ping-pong kept, no cvts on x.
// ============================================================================

static constexpr int NKIT = 40;                    // 5 blocks x 8 chunks of k=32
static constexpr uint32_t A_BYTES = 16384;         // 128 x 32 x 4
static constexpr uint32_t B_BYTES = 32768;         // 256 x 32 x 4
static constexpr uint32_t STAGE_BYTES = A_BYTES + B_BYTES;      // 48KB
static constexpr uint32_t SMEM_TOTAL = 4 * STAGE_BYTES + 1024;  // 197632

// Repacked gathered tf32(RNA) weights, pre-swizzled 32KB SMEM images:
// g_Bp[(o*40+it)*8192 + swz(n*128 + k*4)/4]   (16*40*32KB = 20.97 MB)
__device__ float g_Bp[16 * NKIT * 8192];

// ---------------------------------------------------------------------------
__device__ __forceinline__ uint32_t smem_u32(const void* p) {
    uint32_t a;
    asm("{ .reg .u64 t; cvta.to.shared.u64 t, %1; cvt.u32.u64 %0, t; }"
        : "=r"(a) : "l"(p));
    return a;
}
__device__ __forceinline__ void cpasync16(uint32_t dst, const float* src) {
    asm volatile("cp.async.cg.shared.global [%0], [%1], 16;"
                 :: "r"(dst), "l"(src) : "memory");
}
__device__ __forceinline__ void cp_commit() {
    asm volatile("cp.async.commit_group;" ::: "memory");
}
template <int N>
__device__ __forceinline__ void cp_wait() {
    asm volatile("cp.async.wait_group %0;" :: "n"(N) : "memory");
}
__device__ __forceinline__ void ldsm4(uint32_t* r, uint32_t a) {
    asm volatile("ldmatrix.sync.aligned.m8n8.x4.shared.b16 {%0,%1,%2,%3}, [%4];"
                 : "=r"(r[0]), "=r"(r[1]), "=r"(r[2]), "=r"(r[3]) : "r"(a));
}
__device__ __forceinline__ void mma_tf32(float* c, const uint32_t* a,
                                         uint32_t b0, uint32_t b1) {
    asm volatile(
        "mma.sync.aligned.m16n8k8.row.col.f32.tf32.tf32.f32 "
        "{%0,%1,%2,%3}, {%4,%5,%6,%7}, {%8,%9}, {%0,%1,%2,%3};"
        : "+f"(c[0]), "+f"(c[1]), "+f"(c[2]), "+f"(c[3])
        : "r"(a[0]), "r"(a[1]), "r"(a[2]), "r"(a[3]), "r"(b0), "r"(b1));
}

// ---------------------------------------------------------------------------
// repack: gather + transpose + RNA-round weights into pre-swizzled 32KB tiles
//   grid: (ntile=8, kchunk=8, o*5+a=80), block (32, 8)
// ---------------------------------------------------------------------------
__global__ void __launch_bounds__(256, 4)
repack_kernel(const float* __restrict__ w, const int* __restrict__ fi) {
    const int oa = blockIdx.z;
    const int o = oa / 5, a = oa % 5;
    const int f = fi[o * 5 + a];
    const int g = f / 5, slot = f % 5;
    const int k0 = blockIdx.y * 32;
    const int n0 = blockIdx.x * 32;
    const int c = blockIdx.y;

    __shared__ float t[32][33];
    const int tx = threadIdx.x, ty = threadIdx.y;

    #pragma unroll
    for (int i = 0; i < 4; ++i) {
        int k = ty + i * 8;
        float v = w[((size_t)(g * 256 + k0 + k) * 5 + slot) * 256 + n0 + tx];
        uint32_t u;
        asm("cvt.rna.tf32.f32 %0, %1;" : "=r"(u) : "f"(v));
        t[k][tx] = __uint_as_float(u);
    }
    __syncthreads();

    float* tile = g_Bp + ((size_t)o * NKIT + a * 8 + c) * 8192;
    #pragma unroll
    for (int i = 0; i < 4; ++i) {
        int n = n0 + ty + i * 8;
        uint32_t off = (uint32_t)n * 128u + (uint32_t)tx * 4u;
        uint32_t swz = off ^ ((off >> 3) & 0x70u);
        tile[swz >> 2] = t[tx][ty + i * 8];
    }
}

// ---------------------------------------------------------------------------
// GEMM: grid (o=16, mtile=64), 256 threads, CTA tile 128(M) x 256(N)
//   8 warps in 2(m) x 4(n) grid of 64x64 warp tiles; ping-ponged fragments
// ---------------------------------------------------------------------------
__global__ void __launch_bounds__(256, 1)
gemm_kernel(const float* __restrict__ x, const int* __restrict__ fi,
            float* __restrict__ out) {
    extern __shared__ char smem_raw[];
    const uint32_t sb = (smem_u32(smem_raw) + 1023u) & ~1023u;
    const int tid = (int)threadIdx.x;
    const int wid = tid >> 5;
    const int lane = tid & 31;
    const int o = (int)blockIdx.x;
    const int m_base = (int)blockIdx.y * 128;
    const int warp_m = wid >> 2;   // 0..1  (64 rows each)
    const int warp_n = wid & 3;    // 0..3  (64 cols each)

    int colf[5];
    #pragma unroll
    for (int a = 0; a < 5; ++a) colf[a] = (fi[o * 5 + a] / 5) << 8;

    // ---- producer addressing (all 256 threads) ----
    // A: 128 rows x 8 16B-segs = 1024 segs -> 4 per thread
    const int arow = tid >> 1;                 // 0..127
    const int asub = (tid & 1) * 4;            // segments asub..asub+3 (of 8)
    const float* xrow = x + (size_t)(m_base + arow) * 4096;
    const uint32_t adst_base = (uint32_t)arow * 128u;
    const uint32_t axor = (uint32_t)(arow & 7) << 4;
    // B: 32KB = 2048 segs -> 8 per thread (raw image copy)
    const float* bsrc0 = g_Bp + (size_t)o * NKIT * 8192 + tid * 4;

    auto issue = [&](int it, uint32_t s) {
        const uint32_t st = sb + s * STAGE_BYTES;
        const int col = colf[it >> 3] + (it & 7) * 32;
        const float* asrc = xrow + col + asub * 4;
        #pragma unroll
        for (int j = 0; j < 4; ++j) {
            uint32_t doff = (((uint32_t)(asub + j) * 16u) ^ axor);
            cpasync16(st + adst_base + doff, asrc + j * 4);
        }
        const float* bsrc = bsrc0 + (size_t)it * 8192;
        #pragma unroll
        for (int j = 0; j < 8; ++j)
            cpasync16(st + A_BYTES + (uint32_t)tid * 16u + (uint32_t)j * 4096u,
                      bsrc + j * 1024);
        cp_commit();
    };

    // ---- consumer lane addressing ----
    const int a_tile = lane >> 3;              // 0..3
    const int a_row_l = ((a_tile & 1) << 3) + (lane & 7);
    const int a_ktile = a_tile >> 1;           // 0..1 (k half of 16)
    const int b_khalf = (lane >> 3) & 1;
    const int b_row_l = (((lane >> 4) & 1) << 3) + (lane & 7);

    const uint32_t a_warp_off = (uint32_t)(warp_m * 64) * 128u;
    const uint32_t b_warp_off = A_BYTES + (uint32_t)(warp_n * 64) * 128u;

    float c[4][8][4];
    #pragma unroll
    for (int mi = 0; mi < 4; ++mi)
        #pragma unroll
        for (int ni = 0; ni < 8; ++ni)
            #pragma unroll
            for (int q = 0; q < 4; ++q) c[mi][ni][q] = 0.0f;

    uint32_t af[2][4][4];   // [pingpong][mi][frag]
    uint32_t bf[2][4][4];   // [pingpong][ni2][frag]

    auto load_frags = [&](uint32_t st, int ks, int pb) {
        const uint32_t abw = st + a_warp_off;
        const uint32_t bbw = st + b_warp_off;
        #pragma unroll
        for (int mi = 0; mi < 4; ++mi) {
            int row = mi * 16 + a_row_l;
            uint32_t off = (uint32_t)((ks * 2 + a_ktile) * 16) ^
                           ((uint32_t)(row & 7) << 4);
            ldsm4(af[pb][mi], abw + (uint32_t)row * 128u + off);
        }
        #pragma unroll
        for (int ni2 = 0; ni2 < 4; ++ni2) {
            int n = ni2 * 16 + b_row_l;
            uint32_t off = (uint32_t)((ks * 2 + b_khalf) * 16) ^
                           ((uint32_t)(n & 7) << 4);
            ldsm4(bf[pb][ni2], bbw + (uint32_t)n * 128u + off);
        }
    };

    auto mma_group = [&](int pb) {
        #pragma unroll
        for (int mi = 0; mi < 4; ++mi)
            #pragma unroll
            for (int ni = 0; ni < 8; ++ni) {
                const uint32_t* bp = &bf[pb][ni >> 1][(ni & 1) * 2];
                mma_tf32(c[mi][ni], af[pb][mi], bp[0], bp[1]);
            }
    };

    // prologue: fill 3 stages, land frags for stage 0 / ks 0
    issue(0, 0); issue(1, 1); issue(2, 2);
    cp_wait<2>();
    __syncthreads();
    load_frags(sb, 0, 0);

    #pragma unroll 4
    for (int it = 0; it < NKIT; ++it) {
        const uint32_t buf = (uint32_t)(it & 3);
        const uint32_t st = sb + buf * STAGE_BYTES;

        if (it + 3 < NKIT) issue(it + 3, (uint32_t)((it + 3) & 3));
        else cp_commit();   // keep group numbering advancing

        // ks 0..3 with register ping-pong: load ks+1 while MMAing ks
        load_frags(st, 1, 1);  mma_group(0);
        load_frags(st, 2, 0);  mma_group(1);
        load_frags(st, 3, 1);  mma_group(0);
        mma_group(1);

        cp_wait<2>();
        __syncthreads();
        if (it + 1 < NKIT)
            load_frags(sb + (uint32_t)((it + 1) & 3) * STAGE_BYTES, 0, 0);
    }

    // ---- epilogue: direct stores ----
    const int g = lane >> 2, t4 = lane & 3;
    const int row0 = m_base + warp_m * 64 + g;
    const int col0 = o * 256 + warp_n * 64 + t4 * 2;
    #pragma unroll
    for (int mi = 0; mi < 4; ++mi) {
        #pragma unroll
        for (int ni = 0; ni < 8; ++ni) {
            float* p0 = out + (size_t)(row0 + mi * 16) * 4096 + col0 + ni * 8;
            float* p1 = p0 + 8 * 4096;
            *reinterpret_cast<float2*>(p0) =
                make_float2(c[mi][ni][0], c[mi][ni][1]);
            *reinterpret_cast<float2*>(p1) =
                make_float2(c[mi][ni][2], c[mi][ni][3]);
        }
    }
}

// ---------------------------------------------------------------------------
extern "C" void kernel_launch(void* const* d_in, const int* in_sizes, int n_in,
                              void* d_out, int out_size) {
    const float* x  = (const float*)d_in[0];
    const float* w  = (const float*)d_in[1];
    const int*   fi = (const int*)d_in[2];
    float* out = (float*)d_out;

    repack_kernel<<<dim3(8, 8, 80), dim3(32, 8)>>>(w, fi);

    cudaFuncSetAttribute(gemm_kernel,
                         cudaFuncAttributeMaxDynamicSharedMemorySize, SMEM_TOTAL);
    gemm_kernel<<<dim3(16, 64), 256, SMEM_TOTAL>>>(x, fi, out);
}